// round 9
// baseline (speedup 1.0000x reference)
#include <cuda_runtime.h>
#include <stdint.h>
#include <math.h>

#define BATCH 32
#define SEQ   8400
#define NLAB  80
#define DIM   256
#define NQ    300
#define CAND  512
#define RPB   48              // rows per block -> 175 blocks per batch
#define BPB   (SEQ / RPB)     // 175
#define VPT   33              // ceil(SEQ / 256) values per thread in Phase B

// Scratch (allocation-free per harness rules)
__device__ unsigned int g_scores_u[BATCH * SEQ];
__device__ int          g_topk[BATCH * NQ];
__device__ unsigned int g_arrive[BATCH];          // zero-init; self-resetting

__device__ __forceinline__ unsigned int f32_sortable(float v) {
    unsigned int u = __float_as_uint(v);
    return (u & 0x80000000u) ? ~u : (u | 0x80000000u);  // ascending-order uint
}

// L1-cached global load that ptxas cannot hoist into long-lived registers
__device__ __forceinline__ unsigned int ldca_u32(const unsigned int* p) {
    unsigned int v;
    asm volatile("ld.global.ca.u32 %0, [%1];" : "=r"(v) : "l"(p));
    return v;
}

// ---------------------------------------------------------------------------
// Fused kernel. Phase A: 48 row-maxes per block (best-measured config).
// Arrival via ONE gpu-scope acq_rel atomic per block (no membar, no L1 flush).
// Phase B (last block per batch): exact top-300 via quaternary threshold
// search over [min,max], values re-read through L1 (ld.global.ca), block-scan
// compaction, sync-free all-vs-all ranking. jax tie-break preserved by key
// (score<<32 | SEQ-1-s).
// ---------------------------------------------------------------------------
__global__ void __launch_bounds__(256, 7) fused_scores_topk(const float* __restrict__ cls) {
    __shared__ float              part[RPB * 20];     // 3.84 KB
    __shared__ unsigned int       s_wA[2][8];
    __shared__ unsigned int       s_wB[2][8];
    __shared__ unsigned int       s_woff[8];
    __shared__ unsigned int       s_cnt;
    __shared__ int                s_last;
    __shared__ unsigned long long s_cand[CAND];       // 4 KB

    const int t     = threadIdx.x;
    const int lane  = t & 31;
    const int wid   = t >> 5;
    const int batch = blockIdx.x / BPB;
    const unsigned FULL = 0xFFFFFFFFu;

    // ================= Phase A: 48 row maxes =================
    {
        const float4* base = (const float4*)cls + (size_t)blockIdx.x * (RPB * 20);
        #pragma unroll
        for (int i = 0; i < 4; ++i) {
            int idx = t + 256 * i;
            if (idx < RPB * 20) {
                float4 v = __ldg(&base[idx]);
                part[idx] = fmaxf(fmaxf(v.x, v.y), fmaxf(v.z, v.w));
            }
        }
        __syncthreads();
        if (t < RPB * 4) {                 // 192 threads: 4 per row
            int row = t >> 2;
            int p   = t & 3;
            const float* q = &part[row * 20 + p * 5];
            float m = q[0];
            #pragma unroll
            for (int j = 1; j < 5; ++j) m = fmaxf(m, q[j]);
            m = fmaxf(m, __shfl_xor_sync(FULL, m, 1));
            m = fmaxf(m, __shfl_xor_sync(FULL, m, 2));
            if (p == 0)
                g_scores_u[blockIdx.x * RPB + row] = f32_sortable(m);
        }
    }
    __syncthreads();
    if (t == 0) {
        unsigned int old;
        asm volatile("atom.acq_rel.gpu.add.u32 %0, [%1], 1;"
                     : "=r"(old) : "l"(&g_arrive[batch]) : "memory");
        s_last = (old == BPB - 1);
    }
    __syncthreads();
    if (!s_last) return;

    // ================= Phase B: top-300 (last block of this batch) ==========
    const unsigned int* sc = g_scores_u + batch * SEQ;

    // ---- min/max (search bounds) ----
    unsigned int mx = 0, mn = 0xFFFFFFFFu;
    #pragma unroll
    for (int k = 0; k < VPT; ++k) {
        int idx = t + 256 * k;
        if (idx < SEQ) {
            unsigned int v = ldca_u32(sc + idx);
            mx = max(mx, v); mn = min(mn, v);
        }
    }
    #pragma unroll
    for (int o = 16; o > 0; o >>= 1) {
        mx = max(mx, __shfl_xor_sync(FULL, mx, o));
        mn = min(mn, __shfl_xor_sync(FULL, mn, o));
    }
    if (lane == 0) { s_wA[0][wid] = mx; s_wB[0][wid] = mn; }
    __syncthreads();
    unsigned int M    = s_wA[0][lane & 7];
    unsigned int m_lo = s_wB[0][lane & 7];
    #pragma unroll
    for (int o = 4; o > 0; o >>= 1) {
        M    = max(M,    __shfl_xor_sync(FULL, M,    o));
        m_lo = min(m_lo, __shfl_xor_sync(FULL, m_lo, o));
    }

    // ---- quaternary search on 22-bit codes, 1 barrier/iteration ----
    unsigned int lo = m_lo >> 10, hi = (M >> 10) + 1;
    int parity = 1;
    while (hi - lo > 1) {
        unsigned int d  = hi - lo;
        unsigned int m1 = lo + (d >> 2); if (m1 == lo) m1 = lo + 1;
        unsigned int m2 = lo + (d >> 1); if (m2 == lo) m2 = lo + 1;
        unsigned int m3 = lo + d - (d >> 2); if (m3 >= hi) m3 = hi - 1;
        const unsigned int t1 = m1 << 10, t2 = m2 << 10, t3 = m3 << 10;

        unsigned int c12 = 0, c3 = 0;
        #pragma unroll
        for (int k = 0; k < VPT; ++k) {
            int idx = t + 256 * k;
            if (idx < SEQ) {
                unsigned int v = ldca_u32(sc + idx);
                c12 += (v >= t1) + ((v >= t2) << 16);
                c3  += (v >= t3);
            }
        }
        #pragma unroll
        for (int o = 16; o > 0; o >>= 1) {
            c12 += __shfl_xor_sync(FULL, c12, o);
            c3  += __shfl_xor_sync(FULL, c3,  o);
        }
        if (lane == 0) { s_wA[parity][wid] = c12; s_wB[parity][wid] = c3; }
        __syncthreads();
        unsigned int a  = s_wA[parity][lane & 7];
        unsigned int bb = s_wB[parity][lane & 7];
        #pragma unroll
        for (int o = 4; o > 0; o >>= 1) {
            a  += __shfl_xor_sync(FULL, a,  o);
            bb += __shfl_xor_sync(FULL, bb, o);
        }
        const unsigned int cnt1 = a & 0xFFFFu;
        const unsigned int cnt2 = a >> 16;
        const unsigned int cnt3 = bb;

        if      (cnt3 >= NQ) lo = m3;
        else if (cnt2 >= NQ) { lo = m2; hi = m3; }
        else if (cnt1 >= NQ) { lo = m1; hi = m2; }
        else                 hi = m1;
        parity ^= 1;
    }
    const unsigned int T = lo << 10;

    // ---- compact candidates (block prefix scan, no atomics) ----
    int myc = 0;
    #pragma unroll
    for (int k = 0; k < VPT; ++k) {
        int idx = t + 256 * k;
        if (idx < SEQ) myc += (ldca_u32(sc + idx) >= T);
    }
    int inc = myc;
    #pragma unroll
    for (int o = 1; o < 32; o <<= 1) {
        int t2 = __shfl_up_sync(FULL, inc, o);
        if (lane >= o) inc += t2;
    }
    __syncthreads();                      // protect s_wA reuse
    if (lane == 31) s_wA[0][wid] = (unsigned)inc;
    __syncthreads();
    if (t < 8) {
        unsigned int v = s_wA[0][t];
        unsigned int i2 = v;
        #pragma unroll
        for (int o = 1; o < 8; o <<= 1) {
            unsigned int t2 = __shfl_up_sync(0xFFu, i2, o);
            if (t >= o) i2 += t2;
        }
        s_woff[t] = i2 - v;
        if (t == 7) s_cnt = i2;
    }
    __syncthreads();

    int pos = (int)s_woff[wid] + (inc - myc);
    #pragma unroll
    for (int k = 0; k < VPT; ++k) {
        int idx = t + 256 * k;
        if (idx < SEQ) {
            unsigned int v = ldca_u32(sc + idx);
            if (v >= T) {
                if (pos < CAND)
                    s_cand[pos] = ((unsigned long long)v << 32) |
                                  (unsigned int)(SEQ - 1 - idx);
                ++pos;
            }
        }
    }
    __syncthreads();

    // ---- sync-free ranking: rank = #{j: key_j > key_i} ----
    const int cntC = (int)min(s_cnt, (unsigned)CAND);
    for (int c = t; c < cntC; c += 256) {
        const unsigned long long mine = s_cand[c];
        int rank = 0;
        for (int j = 0; j < cntC; ++j)
            rank += (s_cand[j] > mine);
        if (rank < NQ)
            g_topk[batch * NQ + rank] =
                SEQ - 1 - (int)(unsigned int)(mine & 0xFFFFFFFFull);
    }

    if (t == 0) g_arrive[batch] = 0u;     // reset for graph replay
}

// ---------------------------------------------------------------------------
// Gather kernel (R8 version): 1200 blocks x 256 threads; one warp per query.
// Output layout (flattened tuple, return order):
//   [0]            init_reference_points (B,NQ,4)
//   [+B*NQ*4]      target                (B,NQ,256)
//   [+B*NQ*256]    enc_topk_logits       (B,NQ,80)
//   [+B*NQ*80]     enc_topk_bboxes       (B,NQ,4)
// ---------------------------------------------------------------------------
__global__ void __launch_bounds__(256) gather_kernel(const float* __restrict__ cls,
                              const float* __restrict__ coord,
                              const float* __restrict__ mem,
                              float* __restrict__ out) {
    const int lane = threadIdx.x & 31;
    const int wid  = threadIdx.x >> 5;
    const int bq   = blockIdx.x * 8 + wid;

    float* out_tgt  = out + (size_t)BATCH * NQ * 4;
    float* out_log  = out_tgt + (size_t)BATCH * NQ * DIM;
    float* out_bbox = out_log + (size_t)BATCH * NQ * NLAB;

    const int s = __ldg(&g_topk[bq]);
    const size_t src = (size_t)(bq / NQ) * SEQ + (size_t)s;

    const float4* m4 = (const float4*)(mem + src * DIM);
    float4 m0 = __ldg(&m4[lane]);
    float4 m1 = __ldg(&m4[lane + 32]);
    float4 lg, cd;
    if (lane < 20)
        lg = __ldg(&((const float4*)(cls + src * NLAB))[lane]);
    if (lane == 20)
        cd = __ldg((const float4*)(coord + src * 4));

    float4* o4 = (float4*)(out_tgt + (size_t)bq * DIM);
    o4[lane]      = m0;
    o4[lane + 32] = m1;
    if (lane < 20)
        ((float4*)(out_log + (size_t)bq * NLAB))[lane] = lg;
    if (lane == 20) {
        *(float4*)(out + (size_t)bq * 4) = cd;
        float4 sg;
        sg.x = 1.0f / (1.0f + __expf(-cd.x));
        sg.y = 1.0f / (1.0f + __expf(-cd.y));
        sg.z = 1.0f / (1.0f + __expf(-cd.z));
        sg.w = 1.0f / (1.0f + __expf(-cd.w));
        *(float4*)(out_bbox + (size_t)bq * 4) = sg;
    }
}

// ---------------------------------------------------------------------------
extern "C" void kernel_launch(void* const* d_in, const int* in_sizes, int n_in,
                              void* d_out, int out_size) {
    const float* cls   = (const float*)d_in[0];  // (32, 8400, 80)
    const float* coord = (const float*)d_in[1];  // (32, 8400, 4)
    const float* mem   = (const float*)d_in[2];  // (32, 8400, 256)
    float* out = (float*)d_out;

    fused_scores_topk<<<BATCH * BPB, 256>>>(cls);                    // 5600 blocks
    gather_kernel<<<(BATCH * NQ) / 8, 256>>>(cls, coord, mem, out);  // 1200 blocks
}

// round 10
// speedup vs baseline: 1.4187x; 1.4187x over previous
#include <cuda_runtime.h>
#include <stdint.h>
#include <math.h>

#define BATCH 32
#define SEQ   8400
#define NLAB  80
#define DIM   256
#define NQ    300
#define CAND  512
#define RPB   128     // rows per block in scores kernel (512 thr, 5 ld/thread)

// Scratch (allocation-free per harness rules)
__device__ unsigned int g_scores_u[BATCH * SEQ];  // sortable-uint scores
__device__ int          g_topk[BATCH * NQ];

__device__ __forceinline__ unsigned int f32_sortable(float v) {
    unsigned int u = __float_as_uint(v);
    return (u & 0x80000000u) ? ~u : (u | 0x80000000u);  // ascending-order uint
}

__device__ __forceinline__ void stg_cs_f4(float* p, float4 v) {
    asm volatile("st.global.cs.v4.f32 [%0], {%1,%2,%3,%4};"
                 :: "l"(p), "f"(v.x), "f"(v.y), "f"(v.z), "f"(v.w) : "memory");
}

// ---------------------------------------------------------------------------
// Kernel 1: scores[b][s] = max over 80 labels (sortable uint out).
// 512 threads x exactly 5 float4 loads (fully coalesced, no predication);
// phase 2: one round, 4 lanes per row (stride-5 smem, conflict-free).
// ---------------------------------------------------------------------------
__global__ void __launch_bounds__(512) scores_kernel(const float* __restrict__ cls) {
    __shared__ float part[RPB * 20];  // 2560 floats

    const int t = threadIdx.x;
    const float4* base = (const float4*)cls + (size_t)blockIdx.x * (RPB * 20);

    #pragma unroll
    for (int i = 0; i < 5; ++i) {
        int idx = t + 512 * i;
        float4 v = __ldg(&base[idx]);
        part[idx] = fmaxf(fmaxf(v.x, v.y), fmaxf(v.z, v.w));
    }
    __syncthreads();

    {
        int row = t >> 2;                  // 512 threads -> 128 rows x 4
        int p   = t & 3;
        const float* q = &part[row * 20 + p * 5];
        float m = q[0];
        #pragma unroll
        for (int j = 1; j < 5; ++j) m = fmaxf(m, q[j]);
        m = fmaxf(m, __shfl_xor_sync(0xFFFFFFFFu, m, 1));
        m = fmaxf(m, __shfl_xor_sync(0xFFFFFFFFu, m, 2));
        if (p == 0)
            g_scores_u[blockIdx.x * RPB + row] = f32_sortable(m);
    }
}

// ---------------------------------------------------------------------------
// Kernel 2: per-batch exact top-300 (R8 version, known-good).
// ---------------------------------------------------------------------------
__global__ void __launch_bounds__(1024) topk_kernel() {
    __shared__ unsigned int       s_wA[2][32];
    __shared__ unsigned int       s_wB[2][32];
    __shared__ unsigned int       s_woff[32];
    __shared__ unsigned int       s_cnt;
    __shared__ unsigned long long s_cand[CAND];

    const int b    = blockIdx.x;
    const int tid  = threadIdx.x;
    const int lane = tid & 31;
    const int wid  = tid >> 5;
    const unsigned FULL = 0xFFFFFFFFu;

    const unsigned int* sc = g_scores_u + b * SEQ;

    uint4 va = ((const uint4*)sc)[tid];
    uint4 vb = ((const uint4*)sc)[tid + 1024];
    const bool hasTail = (tid < SEQ - 8192);           // 208
    unsigned int vt = hasTail ? sc[8192 + tid] : 0u;

    unsigned int vv[9];
    int si[9];
    vv[0]=va.x; vv[1]=va.y; vv[2]=va.z; vv[3]=va.w;
    vv[4]=vb.x; vv[5]=vb.y; vv[6]=vb.z; vv[7]=vb.w;
    vv[8]=hasTail ? vt : 0u;
    #pragma unroll
    for (int k = 0; k < 4; ++k) { si[k] = 4*tid + k; si[4+k] = 4096 + 4*tid + k; }
    si[8] = 8192 + tid;

    // ---- block max AND min ----
    unsigned int mx = 0, mn = 0xFFFFFFFFu;
    #pragma unroll
    for (int k = 0; k < 8; ++k) { mx = max(mx, vv[k]); mn = min(mn, vv[k]); }
    if (hasTail) { mx = max(mx, vv[8]); mn = min(mn, vv[8]); }
    #pragma unroll
    for (int o = 16; o > 0; o >>= 1) {
        mx = max(mx, __shfl_xor_sync(FULL, mx, o));
        mn = min(mn, __shfl_xor_sync(FULL, mn, o));
    }
    if (lane == 0) { s_wA[0][wid] = mx; s_wB[0][wid] = mn; }
    __syncthreads();
    unsigned int M = s_wA[0][lane];
    unsigned int m_lo = s_wB[0][lane];
    #pragma unroll
    for (int o = 16; o > 0; o >>= 1) {
        M    = max(M,    __shfl_xor_sync(FULL, M,    o));
        m_lo = min(m_lo, __shfl_xor_sync(FULL, m_lo, o));
    }

    // ---- quaternary search on 22-bit codes, 1 barrier/iteration ----
    unsigned int lo = m_lo >> 10, hi = (M >> 10) + 1;
    int parity = 1;
    while (hi - lo > 1) {
        unsigned int d  = hi - lo;
        unsigned int m1 = lo + (d >> 2); if (m1 == lo) m1 = lo + 1;
        unsigned int m2 = lo + (d >> 1); if (m2 == lo) m2 = lo + 1;
        unsigned int m3 = lo + d - (d >> 2); if (m3 >= hi) m3 = hi - 1;
        const unsigned int t1 = m1 << 10, t2 = m2 << 10, t3 = m3 << 10;

        unsigned int c12 = 0, c3 = 0;
        #pragma unroll
        for (int k = 0; k < 8; ++k) {
            unsigned int v = vv[k];
            c12 += (v >= t1) + ((v >= t2) << 16);
            c3  += (v >= t3);
        }
        if (hasTail) {
            unsigned int v = vv[8];
            c12 += (v >= t1) + ((v >= t2) << 16);
            c3  += (v >= t3);
        }
        #pragma unroll
        for (int o = 16; o > 0; o >>= 1) {
            c12 += __shfl_xor_sync(FULL, c12, o);
            c3  += __shfl_xor_sync(FULL, c3,  o);
        }
        if (lane == 0) { s_wA[parity][wid] = c12; s_wB[parity][wid] = c3; }
        __syncthreads();
        unsigned int a  = s_wA[parity][lane];
        unsigned int bb = s_wB[parity][lane];
        #pragma unroll
        for (int o = 16; o > 0; o >>= 1) {
            a  += __shfl_xor_sync(FULL, a,  o);
            bb += __shfl_xor_sync(FULL, bb, o);
        }
        const unsigned int cnt1 = a & 0xFFFFu;
        const unsigned int cnt2 = a >> 16;
        const unsigned int cnt3 = bb;

        if      (cnt3 >= NQ) lo = m3;
        else if (cnt2 >= NQ) { lo = m2; hi = m3; }
        else if (cnt1 >= NQ) { lo = m1; hi = m2; }
        else                 hi = m1;
        parity ^= 1;
    }
    const unsigned int T = lo << 10;

    // ---- compact candidates via block prefix scan ----
    bool hit[9];
    int myc = 0;
    #pragma unroll
    for (int k = 0; k < 8; ++k) { hit[k] = (vv[k] >= T); myc += hit[k]; }
    hit[8] = hasTail && (vv[8] >= T); myc += hit[8];

    int inc = myc;
    #pragma unroll
    for (int o = 1; o < 32; o <<= 1) {
        int t2 = __shfl_up_sync(FULL, inc, o);
        if (lane >= o) inc += t2;
    }
    __syncthreads();               // protect s_wA reuse from search phase
    if (lane == 31) s_wA[0][wid] = (unsigned)inc;
    __syncthreads();
    if (tid < 32) {
        unsigned int v = s_wA[0][tid];
        unsigned int i2 = v;
        #pragma unroll
        for (int o = 1; o < 32; o <<= 1) {
            unsigned int t2 = __shfl_up_sync(FULL, i2, o);
            if (tid >= o) i2 += t2;
        }
        s_woff[tid] = i2 - v;
        if (tid == 31) s_cnt = i2;
    }
    __syncthreads();

    int pos = (int)s_woff[wid] + (inc - myc);
    #pragma unroll
    for (int k = 0; k < 9; ++k) {
        if (hit[k]) {
            if (pos < CAND)
                s_cand[pos] = ((unsigned long long)vv[k] << 32) |
                              (unsigned int)(SEQ - 1 - si[k]);
            ++pos;
        }
    }
    __syncthreads();

    // ---- sync-free ranking: rank = #{j: key_j > key_i} ----
    const int cntC = (int)min(s_cnt, (unsigned)CAND);
    if (tid < cntC) {
        const unsigned long long mine = s_cand[tid];
        int rank = 0;
        for (int j = 0; j < cntC; ++j)
            rank += (s_cand[j] > mine);
        if (rank < NQ)
            g_topk[b * NQ + rank] =
                SEQ - 1 - (int)(unsigned int)(mine & 0xFFFFFFFFull);
    }
}

// ---------------------------------------------------------------------------
// Kernel 3: gather. 1200 blocks x 256 threads; one warp per query.
// Small loads issued first so all 4 gather LDGs overlap; big target rows
// stored with .cs streaming hint (consumed once, keep L2 for cls).
// Output layout (flattened tuple, return order):
//   [0]            init_reference_points (B,NQ,4)
//   [+B*NQ*4]      target                (B,NQ,256)
//   [+B*NQ*256]    enc_topk_logits       (B,NQ,80)
//   [+B*NQ*80]     enc_topk_bboxes       (B,NQ,4)
// ---------------------------------------------------------------------------
__global__ void __launch_bounds__(256) gather_kernel(const float* __restrict__ cls,
                              const float* __restrict__ coord,
                              const float* __restrict__ mem,
                              float* __restrict__ out) {
    const int lane = threadIdx.x & 31;
    const int wid  = threadIdx.x >> 5;
    const int bq   = blockIdx.x * 8 + wid;

    float* out_tgt  = out + (size_t)BATCH * NQ * 4;
    float* out_log  = out_tgt + (size_t)BATCH * NQ * DIM;
    float* out_bbox = out_log + (size_t)BATCH * NQ * NLAB;

    const int s = __ldg(&g_topk[bq]);                 // broadcast load
    const size_t src = (size_t)(bq / NQ) * SEQ + (size_t)s;

    // small gathers first, then the two big row loads (all independent)
    float4 lg, cd;
    if (lane < 20)
        lg = __ldg(&((const float4*)(cls + src * NLAB))[lane]);
    if (lane == 20)
        cd = __ldg((const float4*)(coord + src * 4));
    const float4* m4 = (const float4*)(mem + src * DIM);
    float4 m0 = __ldg(&m4[lane]);
    float4 m1 = __ldg(&m4[lane + 32]);

    float* o = out_tgt + (size_t)bq * DIM;
    stg_cs_f4(o + 4 * lane,        m0);
    stg_cs_f4(o + 4 * (lane + 32), m1);
    if (lane < 20)
        stg_cs_f4(out_log + (size_t)bq * NLAB + 4 * lane, lg);
    if (lane == 20) {
        stg_cs_f4(out + (size_t)bq * 4, cd);
        float4 sg;
        sg.x = 1.0f / (1.0f + __expf(-cd.x));
        sg.y = 1.0f / (1.0f + __expf(-cd.y));
        sg.z = 1.0f / (1.0f + __expf(-cd.z));
        sg.w = 1.0f / (1.0f + __expf(-cd.w));
        stg_cs_f4(out_bbox + (size_t)bq * 4, sg);
    }
}

// ---------------------------------------------------------------------------
extern "C" void kernel_launch(void* const* d_in, const int* in_sizes, int n_in,
                              void* d_out, int out_size) {
    const float* cls   = (const float*)d_in[0];  // (32, 8400, 80)
    const float* coord = (const float*)d_in[1];  // (32, 8400, 4)
    const float* mem   = (const float*)d_in[2];  // (32, 8400, 256)
    float* out = (float*)d_out;

    scores_kernel<<<(BATCH * SEQ) / RPB, 512>>>(cls);      // 2100 blocks
    topk_kernel<<<BATCH, 1024>>>();                        // 32 blocks
    gather_kernel<<<(BATCH * NQ) / 8, 256>>>(cls, coord, mem, out);  // 1200 blocks
}